// round 15
// baseline (speedup 1.0000x reference)
#include <cuda_runtime.h>
#include <cuda_fp16.h>
#include <cstdint>

#define NN 100000
#define NE 6400000
#define DIN 128
#define HID 16
#define TOT (NN * HID)
#define ROW 128            // padded CSR row capacity (deg ~ Poisson(64); P(>128) ~ 1e-15)
#define NB1 391            // ceil(NN/256)
#define LNB 128            // nodes per ln_gemm block
#define LNG 782            // ceil(NN/128)

// ---------------- scratch (static device globals; no allocation) ----------------
__device__ __align__(16) __half g_h1[TOT];   // fp16: dinv[n] * (xn @ W1)
__device__ __align__(16) __half g_t[TOT];    // fp16: dinv[n] * (dropout(relu(conv1)) @ W2)
__device__ __align__(16) float  g_a1[TOT];   // conv1 gather sums (fp32)
__device__ __align__(16) float  g_a2[TOT];   // conv2 gather sums (fp32)
__device__ float g_dinv[NN];
__device__ int   g_cnt[NN];                  // fill cursor / degree; re-zeroed each replay
__device__ int   g_end[NN];                  // absolute row end = n*ROW + deg
__device__ int   g_csrc[NN * ROW];           // padded CSR: src per slot (51.2 MB)

// ---------------- JAX Threefry-2x32 (20 rounds), bit-exact ----------------
__host__ __device__ __forceinline__ void threefry2x32(
    uint32_t k0, uint32_t k1, uint32_t x0, uint32_t x1,
    uint32_t& o0, uint32_t& o1)
{
    uint32_t ks2 = k0 ^ k1 ^ 0x1BD11BDAu;
    x0 += k0; x1 += k1;
#define TF_R(r) { x0 += x1; x1 = (x1 << r) | (x1 >> (32 - r)); x1 ^= x0; }
    TF_R(13) TF_R(15) TF_R(26) TF_R(6)
    x0 += k1;  x1 += ks2 + 1u;
    TF_R(17) TF_R(29) TF_R(16) TF_R(24)
    x0 += ks2; x1 += k0 + 2u;
    TF_R(13) TF_R(15) TF_R(26) TF_R(6)
    x0 += k0;  x1 += k1 + 3u;
    TF_R(17) TF_R(29) TF_R(16) TF_R(24)
    x0 += k1;  x1 += ks2 + 4u;
    TF_R(13) TF_R(15) TF_R(26) TF_R(6)
    x0 += ks2; x1 += k0 + 5u;
#undef TF_R
    o0 = x0; o1 = x1;
}

// Partitionable-mode random_bits: counter (0, i); output = o0 ^ o1.
__device__ __forceinline__ float dropout_elem(float h, uint32_t k0, uint32_t k1, uint32_t i)
{
    uint32_t o0, o1;
    threefry2x32(k0, k1, 0u, i, o0, o1);
    uint32_t bits = o0 ^ o1;
    float u = __uint_as_float((bits >> 9) | 0x3F800000u) - 1.0f;
    return (u >= 0.3f) ? (h / 0.7f) : 0.0f;
}

// load 4 consecutive halfs (8B) -> float4
__device__ __forceinline__ float4 ld_h4(const __half* p)
{
    uint2 r = *(const uint2*)p;
    __half2 h0 = *(__half2*)&r.x, h1 = *(__half2*)&r.y;
    float2 f0 = __half22float2(h0), f1 = __half22float2(h1);
    return make_float4(f0.x, f0.y, f1.x, f1.y);
}

// ---------------- padded CSR fill: no histogram/scan needed ----------------
__global__ void k_fill(const int4* __restrict__ src4, const int4* __restrict__ dst4)
{
    unsigned i = blockIdx.x * blockDim.x + threadIdx.x;   // grid covers NE/4 exactly
    int4 s = src4[i];
    int4 d = dst4[i];
    int p0 = atomicAdd(&g_cnt[d.x], 1);
    int p1 = atomicAdd(&g_cnt[d.y], 1);
    int p2 = atomicAdd(&g_cnt[d.z], 1);
    int p3 = atomicAdd(&g_cnt[d.w], 1);
    if (p0 < ROW) g_csrc[(size_t)d.x * ROW + p0] = s.x;
    if (p1 < ROW) g_csrc[(size_t)d.y * ROW + p1] = s.y;
    if (p2 < ROW) g_csrc[(size_t)d.z * ROW + p2] = s.z;
    if (p3 < ROW) g_csrc[(size_t)d.w * ROW + p3] = s.w;
}

// degree -> dinv + row end; re-zero cnt (replay invariant)
__global__ void k_dinv()
{
    unsigned i = blockIdx.x * blockDim.x + threadIdx.x;
    if (i < NN) {
        int c = g_cnt[i];
        g_end[i] = (int)(i * ROW) + c;
        g_dinv[i] = rsqrtf((float)(c + 1));   // +1 self-loop
        g_cnt[i] = 0;
    }
}

// ---------------- LayerNorm + GEMM1: smem-staged, thread-per-node, dinv-prescaled fp16 out ------
// dynamic smem: xs[128][129] fp32 (66048 B). static: W1 (8KB) + gamma/beta (1KB).
__global__ __launch_bounds__(LNB) void k_ln_gemm(
    const float* __restrict__ x,
    const float* __restrict__ gamma, const float* __restrict__ beta,
    const float* __restrict__ W1)
{
    extern __shared__ float xs[];                // [LNB][129]
    __shared__ float  ws[DIN * HID];             // W1 row-major [k][j]
    __shared__ float2 gb[DIN];                   // (gamma, beta)

    unsigned t = threadIdx.x;
    unsigned base = blockIdx.x * LNB;
    int nvalid = min(LNB, NN - (int)base);

    for (int i = t; i < DIN * HID; i += LNB) ws[i] = W1[i];
    gb[t] = make_float2(gamma[t], beta[t]);      // LNB == DIN == 128

    const float4* xp4 = (const float4*)(x + (size_t)base * DIN);
    for (int i = t; i < nvalid * 32; i += LNB) {
        float4 v = xp4[i];
        int node = i >> 5, f = (i & 31) * 4;
        float* row = xs + node * 129 + f;
        row[0] = v.x; row[1] = v.y; row[2] = v.z; row[3] = v.w;
    }
    __syncthreads();

    if ((int)t < nvalid) {
        unsigned n = base + t;
        const float* row = xs + t * 129;

        float s0 = 0.f, s1 = 0.f, s2 = 0.f, s3 = 0.f;
        float q0 = 0.f, q1 = 0.f, q2 = 0.f, q3 = 0.f;
#pragma unroll
        for (int k = 0; k < DIN; k += 4) {
            float a = row[k], b = row[k + 1], c = row[k + 2], d = row[k + 3];
            s0 += a; s1 += b; s2 += c; s3 += d;
            q0 = fmaf(a, a, q0); q1 = fmaf(b, b, q1);
            q2 = fmaf(c, c, q2); q3 = fmaf(d, d, q3);
        }
        float s  = (s0 + s1) + (s2 + s3);
        float ss = (q0 + q1) + (q2 + q3);
        float mu  = s * (1.0f / 128.0f);
        float var = ss * (1.0f / 128.0f) - mu * mu;
        float rs  = rsqrtf(var + 1e-5f);
        float di  = g_dinv[n];

        float acc[HID];
#pragma unroll
        for (int j = 0; j < HID; ++j) acc[j] = 0.f;

        for (int k = 0; k < DIN; ++k) {
            float2 g2 = gb[k];
            float xn = fmaf((row[k] - mu) * rs, g2.x, g2.y);
            const float4* wr = (const float4*)(ws + k * HID);
            float4 w0 = wr[0], w1 = wr[1], w2 = wr[2], w3 = wr[3];
            acc[0]  = fmaf(xn, w0.x, acc[0]);  acc[1]  = fmaf(xn, w0.y, acc[1]);
            acc[2]  = fmaf(xn, w0.z, acc[2]);  acc[3]  = fmaf(xn, w0.w, acc[3]);
            acc[4]  = fmaf(xn, w1.x, acc[4]);  acc[5]  = fmaf(xn, w1.y, acc[5]);
            acc[6]  = fmaf(xn, w1.z, acc[6]);  acc[7]  = fmaf(xn, w1.w, acc[7]);
            acc[8]  = fmaf(xn, w2.x, acc[8]);  acc[9]  = fmaf(xn, w2.y, acc[9]);
            acc[10] = fmaf(xn, w2.z, acc[10]); acc[11] = fmaf(xn, w2.w, acc[11]);
            acc[12] = fmaf(xn, w3.x, acc[12]); acc[13] = fmaf(xn, w3.y, acc[13]);
            acc[14] = fmaf(xn, w3.z, acc[14]); acc[15] = fmaf(xn, w3.w, acc[15]);
        }

        uint4 o0, o1;
        __half2* ph = (__half2*)&o0;
#pragma unroll
        for (int j = 0; j < 4; ++j)
            ph[j] = __floats2half2_rn(acc[2 * j] * di, acc[2 * j + 1] * di);
        ph = (__half2*)&o1;
#pragma unroll
        for (int j = 0; j < 4; ++j)
            ph[j] = __floats2half2_rn(acc[8 + 2 * j] * di, acc[9 + 2 * j] * di);
        *(uint4*)(g_h1 + (size_t)n * 16)     = o0;
        *(uint4*)(g_h1 + (size_t)n * 16 + 8) = o1;
    }
}

// ---------------- CSR gather (fp16 h): warp per dst node, 4 lanes/edge, 4x unroll ----------------
// pass=0: h=g_h1 acc=g_a1 ; pass=1: h=g_t acc=g_a2 (selected DEVICE-side)
__global__ __launch_bounds__(256) void k_gather(int pass)
{
    const __half* __restrict__ h = pass ? g_t : g_h1;
    float* __restrict__ acc      = pass ? g_a2 : g_a1;

    unsigned n = blockIdx.x * 8 + (threadIdx.x >> 5);   // 12500 * 8 = 100000 exactly
    unsigned l = threadIdx.x & 31;
    unsigned g = l >> 2, c = l & 3;
    int end = __ldg(&g_end[n]);
    int e = (int)(n * ROW) + (int)g;

    float4 a0 = make_float4(0.f, 0.f, 0.f, 0.f);
    float4 a1 = make_float4(0.f, 0.f, 0.f, 0.f);
    float4 a2 = make_float4(0.f, 0.f, 0.f, 0.f);
    float4 a3 = make_float4(0.f, 0.f, 0.f, 0.f);
    for (; e + 24 < end; e += 32) {                // four edges in flight per group
        int s0 = __ldg(&g_csrc[e]);
        int s1 = __ldg(&g_csrc[e + 8]);
        int s2 = __ldg(&g_csrc[e + 16]);
        int s3 = __ldg(&g_csrc[e + 24]);
        float4 h0 = ld_h4(h + (size_t)s0 * 16 + c * 4);
        float4 h1 = ld_h4(h + (size_t)s1 * 16 + c * 4);
        float4 h2 = ld_h4(h + (size_t)s2 * 16 + c * 4);
        float4 h3 = ld_h4(h + (size_t)s3 * 16 + c * 4);
        a0.x += h0.x; a0.y += h0.y; a0.z += h0.z; a0.w += h0.w;
        a1.x += h1.x; a1.y += h1.y; a1.z += h1.z; a1.w += h1.w;
        a2.x += h2.x; a2.y += h2.y; a2.z += h2.z; a2.w += h2.w;
        a3.x += h3.x; a3.y += h3.y; a3.z += h3.z; a3.w += h3.w;
    }
    for (; e < end; e += 8) {
        int s = __ldg(&g_csrc[e]);
        float4 hv = ld_h4(h + (size_t)s * 16 + c * 4);
        a0.x += hv.x; a0.y += hv.y; a0.z += hv.z; a0.w += hv.w;
    }
    a0.x += a1.x + a2.x + a3.x;
    a0.y += a1.y + a2.y + a3.y;
    a0.z += a1.z + a2.z + a3.z;
    a0.w += a1.w + a2.w + a3.w;

#pragma unroll
    for (int d = 4; d < 32; d <<= 1) {
        a0.x += __shfl_xor_sync(0xffffffffu, a0.x, d);
        a0.y += __shfl_xor_sync(0xffffffffu, a0.y, d);
        a0.z += __shfl_xor_sync(0xffffffffu, a0.z, d);
        a0.w += __shfl_xor_sync(0xffffffffu, a0.w, d);
    }
    if (l < 4) {
        float4 hv = ld_h4(h + (size_t)n * 16 + c * 4);   // self-loop
        a0.x += hv.x; a0.y += hv.y; a0.z += hv.z; a0.w += hv.w;
        *(float4*)(acc + (size_t)n * 16 + c * 4) = a0;
    }
}

// ---------------- post conv1: dinv*sum + b1, relu, dropout(dk1), @W2, prescale, fp16 out ----------------
__global__ void k_post1(const float* __restrict__ b1, const float* __restrict__ W2,
                        uint32_t k0, uint32_t k1)
{
    __shared__ float w2s[256];
    unsigned tid = threadIdx.x;
    w2s[tid] = W2[tid];
    __syncthreads();

    unsigned idx = blockIdx.x * blockDim.x + tid;   // grid covers TOT exactly
    unsigned n = idx >> 4, j = idx & 15;
    float di = g_dinv[n];
    float v = fmaxf(fmaf(di, g_a1[idx], b1[j]), 0.0f);
    v = dropout_elem(v, k0, k1, idx);

    float acc = 0.0f;
#pragma unroll
    for (int jj = 0; jj < 16; ++jj) {
        float hv = __shfl_sync(0xffffffffu, v, jj, 16);
        acc = fmaf(hv, w2s[jj * 16 + j], acc);
    }
    acc *= di;
    float acc2 = __shfl_down_sync(0xffffffffu, acc, 1);
    if (!(j & 1))
        *(__half2*)(g_t + (size_t)n * 16 + j) = __floats2half2_rn(acc, acc2);
}

// ---------------- final: dinv*sum + b2, relu, dropout(dk2) -> out ----------------
__global__ void k_final(float* __restrict__ out, const float* __restrict__ b2,
                        uint32_t k0, uint32_t k1)
{
    unsigned idx = blockIdx.x * blockDim.x + threadIdx.x;   // covers TOT exactly
    unsigned n = idx >> 4, j = idx & 15;
    float v = fmaxf(fmaf(g_dinv[n], g_a2[idx], b2[j]), 0.0f);
    out[idx] = dropout_elem(v, k0, k1, idx);
}

// ---------------- launch ----------------
extern "C" void kernel_launch(void* const* d_in, const int* in_sizes, int n_in,
                              void* d_out, int out_size)
{
    const float* x     = (const float*)d_in[0];
    const int*   ei    = (const int*)d_in[1];
    const float* gamma = (const float*)d_in[2];
    const float* beta  = (const float*)d_in[3];
    const float* W1    = (const float*)d_in[4];
    const float* b1    = (const float*)d_in[5];
    const float* W2    = (const float*)d_in[6];
    const float* b2    = (const float*)d_in[7];
    float* out = (float*)d_out;

    const int4* src4 = (const int4*)ei;            // edge_index[0]
    const int4* dst4 = (const int4*)(ei + NE);     // edge_index[1]

    // JAX partitionable split: dk1 = threefry(key,(0,0)), dk2 = threefry(key,(0,1))
    uint32_t A0, A1, B0, B1;
    threefry2x32(0u, 42u, 0u, 0u, A0, A1);
    threefry2x32(0u, 42u, 0u, 1u, B0, B1);

    const int xs_bytes = LNB * 129 * (int)sizeof(float);   // 66048
    cudaFuncSetAttribute(k_ln_gemm, cudaFuncAttributeMaxDynamicSharedMemorySize, xs_bytes);

    k_fill<<<NE / 4 / 256, 256>>>(src4, dst4);
    k_dinv<<<NB1, 256>>>();
    k_ln_gemm<<<LNG, LNB, xs_bytes>>>(x, gamma, beta, W1);
    k_gather<<<12500, 256>>>(0);
    k_post1<<<TOT / 256, 256>>>(b1, W2, A0, A1);
    k_gather<<<12500, 256>>>(1);
    k_final<<<TOT / 256, 256>>>(out, b2, B0, B1);
}

// round 16
// speedup vs baseline: 1.0187x; 1.0187x over previous
#include <cuda_runtime.h>
#include <cuda_fp16.h>
#include <cstdint>

#define NN 100000
#define NE 6400000
#define DIN 128
#define HID 16
#define TOT (NN * HID)
#define ROW 128            // padded CSR row capacity (deg ~ Poisson(64); P(>128) ~ 1e-15)
#define NB1 391            // ceil(NN/256)

// ---------------- scratch (static device globals; no allocation) ----------------
__device__ __align__(16) __half g_h1[TOT];   // fp16: dinv[n] * (xn @ W1)
__device__ __align__(16) __half g_t[TOT];    // fp16: dinv[n] * (dropout(relu(conv1)) @ W2)
__device__ __align__(16) float  g_a1[TOT];   // conv1 gather sums (fp32)
__device__ __align__(16) float  g_a2[TOT];   // conv2 gather sums (fp32)
__device__ float g_dinv[NN];
__device__ int   g_cnt[NN];                  // fill cursor / degree; re-zeroed each replay
__device__ int   g_end[NN];                  // absolute row end = n*ROW + deg
__device__ int   g_csrc[NN * ROW];           // padded CSR: src per slot (51.2 MB)

// ---------------- JAX Threefry-2x32 (20 rounds), bit-exact ----------------
__host__ __device__ __forceinline__ void threefry2x32(
    uint32_t k0, uint32_t k1, uint32_t x0, uint32_t x1,
    uint32_t& o0, uint32_t& o1)
{
    uint32_t ks2 = k0 ^ k1 ^ 0x1BD11BDAu;
    x0 += k0; x1 += k1;
#define TF_R(r) { x0 += x1; x1 = (x1 << r) | (x1 >> (32 - r)); x1 ^= x0; }
    TF_R(13) TF_R(15) TF_R(26) TF_R(6)
    x0 += k1;  x1 += ks2 + 1u;
    TF_R(17) TF_R(29) TF_R(16) TF_R(24)
    x0 += ks2; x1 += k0 + 2u;
    TF_R(13) TF_R(15) TF_R(26) TF_R(6)
    x0 += k0;  x1 += k1 + 3u;
    TF_R(17) TF_R(29) TF_R(16) TF_R(24)
    x0 += k1;  x1 += ks2 + 4u;
    TF_R(13) TF_R(15) TF_R(26) TF_R(6)
    x0 += ks2; x1 += k0 + 5u;
#undef TF_R
    o0 = x0; o1 = x1;
}

// Partitionable-mode random_bits: counter (0, i); output = o0 ^ o1.
__device__ __forceinline__ float dropout_elem(float h, uint32_t k0, uint32_t k1, uint32_t i)
{
    uint32_t o0, o1;
    threefry2x32(k0, k1, 0u, i, o0, o1);
    uint32_t bits = o0 ^ o1;
    float u = __uint_as_float((bits >> 9) | 0x3F800000u) - 1.0f;
    return (u >= 0.3f) ? (h / 0.7f) : 0.0f;
}

// load 4 consecutive halfs (8B) -> float4
__device__ __forceinline__ float4 ld_h4(const __half* p)
{
    uint2 r = *(const uint2*)p;
    __half2 h0 = *(__half2*)&r.x, h1 = *(__half2*)&r.y;
    float2 f0 = __half22float2(h0), f1 = __half22float2(h1);
    return make_float4(f0.x, f0.y, f1.x, f1.y);
}

// ---------------- padded CSR fill: 2x int4 per thread = 8 atomic chains in flight ----------------
__global__ void k_fill(const int4* __restrict__ src4, const int4* __restrict__ dst4)
{
    unsigned i = blockIdx.x * blockDim.x + threadIdx.x;   // grid covers NE/8 exactly
    const unsigned OFS = NE / 8;                          // 800000 int4 elements
    int4 s0 = src4[i],       d0 = dst4[i];
    int4 s1 = src4[i + OFS], d1 = dst4[i + OFS];

    int p0 = atomicAdd(&g_cnt[d0.x], 1);
    int p1 = atomicAdd(&g_cnt[d0.y], 1);
    int p2 = atomicAdd(&g_cnt[d0.z], 1);
    int p3 = atomicAdd(&g_cnt[d0.w], 1);
    int p4 = atomicAdd(&g_cnt[d1.x], 1);
    int p5 = atomicAdd(&g_cnt[d1.y], 1);
    int p6 = atomicAdd(&g_cnt[d1.z], 1);
    int p7 = atomicAdd(&g_cnt[d1.w], 1);

    if (p0 < ROW) g_csrc[(size_t)d0.x * ROW + p0] = s0.x;
    if (p1 < ROW) g_csrc[(size_t)d0.y * ROW + p1] = s0.y;
    if (p2 < ROW) g_csrc[(size_t)d0.z * ROW + p2] = s0.z;
    if (p3 < ROW) g_csrc[(size_t)d0.w * ROW + p3] = s0.w;
    if (p4 < ROW) g_csrc[(size_t)d1.x * ROW + p4] = s1.x;
    if (p5 < ROW) g_csrc[(size_t)d1.y * ROW + p5] = s1.y;
    if (p6 < ROW) g_csrc[(size_t)d1.z * ROW + p6] = s1.z;
    if (p7 < ROW) g_csrc[(size_t)d1.w * ROW + p7] = s1.w;
}

// degree -> dinv + row end; re-zero cnt (replay invariant)
__global__ void k_dinv()
{
    unsigned i = blockIdx.x * blockDim.x + threadIdx.x;
    if (i < NN) {
        int c = g_cnt[i];
        g_end[i] = (int)(i * ROW) + c;
        g_dinv[i] = rsqrtf((float)(c + 1));   // +1 self-loop
        g_cnt[i] = 0;
    }
}

// ---------------- LayerNorm + GEMM1 (warp per node), fp16 W cache, dinv-prescaled fp16 out --------
__global__ __launch_bounds__(256, 3) void k_ln_gemm(
    const float* __restrict__ x,
    const float* __restrict__ gamma, const float* __restrict__ beta,
    const float* __restrict__ W1)
{
    unsigned l = threadIdx.x & 31;
    unsigned warp = blockIdx.x * (blockDim.x >> 5) + (threadIdx.x >> 5);
    unsigned nwarps = gridDim.x * (blockDim.x >> 5);

    float4 g4 = *(const float4*)(gamma + l * 4);
    float4 b4 = *(const float4*)(beta + l * 4);
    // W1 rows 4l..4l+3 cached as fp16 (32 regs instead of 64)
    __half2 w[32];
#pragma unroll
    for (int c = 0; c < 4; ++c)
#pragma unroll
        for (int q = 0; q < 4; ++q) {
            float4 wv = *(const float4*)(W1 + (size_t)(l * 4 + c) * 16 + q * 4);
            w[(c * 4 + q) * 2 + 0] = __floats2half2_rn(wv.x, wv.y);
            w[(c * 4 + q) * 2 + 1] = __floats2half2_rn(wv.z, wv.w);
        }

    unsigned n = warp;
    float4 xv = make_float4(0.f, 0.f, 0.f, 0.f);
    float di = 0.f;
    if (n < NN) {
        xv = *(const float4*)(x + (size_t)n * DIN + l * 4);
        di = g_dinv[n];
    }

    while (n < NN) {
        unsigned n2 = n + nwarps;                 // prefetch next node
        float4 xv2 = make_float4(0.f, 0.f, 0.f, 0.f);
        float di2 = 0.f;
        if (n2 < NN) {
            xv2 = *(const float4*)(x + (size_t)n2 * DIN + l * 4);
            di2 = g_dinv[n2];
        }

        float s  = xv.x + xv.y + xv.z + xv.w;
        float ss = xv.x * xv.x + xv.y * xv.y + xv.z * xv.z + xv.w * xv.w;
#pragma unroll
        for (int d = 16; d >= 1; d >>= 1) {
            s  += __shfl_xor_sync(0xffffffffu, s,  d);
            ss += __shfl_xor_sync(0xffffffffu, ss, d);
        }
        float mu  = s * (1.0f / 128.0f);
        float var = ss * (1.0f / 128.0f) - mu * mu;
        float rs  = rsqrtf(var + 1e-5f);

        float xn[4];
        xn[0] = (xv.x - mu) * rs * g4.x + b4.x;
        xn[1] = (xv.y - mu) * rs * g4.y + b4.y;
        xn[2] = (xv.z - mu) * rs * g4.z + b4.z;
        xn[3] = (xv.w - mu) * rs * g4.w + b4.w;

        float p[16];
#pragma unroll
        for (int j = 0; j < 16; ++j) p[j] = 0.0f;
#pragma unroll
        for (int c = 0; c < 4; ++c) {
#pragma unroll
            for (int q = 0; q < 4; ++q) {
                float2 wa = __half22float2(w[(c * 4 + q) * 2 + 0]);
                float2 wb = __half22float2(w[(c * 4 + q) * 2 + 1]);
                p[q * 4 + 0] = fmaf(xn[c], wa.x, p[q * 4 + 0]);
                p[q * 4 + 1] = fmaf(xn[c], wa.y, p[q * 4 + 1]);
                p[q * 4 + 2] = fmaf(xn[c], wb.x, p[q * 4 + 2]);
                p[q * 4 + 3] = fmaf(xn[c], wb.y, p[q * 4 + 3]);
            }
        }
        {
            bool hi;
#define RED_STEP(D, M)                                                        \
            hi = (l & D) != 0;                                                \
            _Pragma("unroll")                                                 \
            for (int i = 0; i < M; ++i) {                                     \
                float send  = hi ? p[i] : p[i + M];                           \
                float other = __shfl_xor_sync(0xffffffffu, send, D);          \
                float keep  = hi ? p[i + M] : p[i];                           \
                p[i] = keep + other;                                          \
            }
            RED_STEP(16, 8) RED_STEP(8, 4) RED_STEP(4, 2) RED_STEP(2, 1)
#undef RED_STEP
            p[0] += __shfl_xor_sync(0xffffffffu, p[0], 1);
        }
        // all lanes hold feature (l>>1); pack fp16 pairs on lanes with l%4==0
        {
            float val = p[0] * di;
            float vnx = __shfl_down_sync(0xffffffffu, val, 2);
            if ((l & 3) == 0)
                *(__half2*)(g_h1 + (size_t)n * 16 + (l >> 1)) = __floats2half2_rn(val, vnx);
        }

        n = n2; xv = xv2; di = di2;
    }
}

// ---------------- CSR gather (fp16 h): warp per dst node, 4 lanes/edge, 4x unroll ----------------
// pass=0: h=g_h1 acc=g_a1 ; pass=1: h=g_t acc=g_a2 (selected DEVICE-side)
__global__ __launch_bounds__(256) void k_gather(int pass)
{
    const __half* __restrict__ h = pass ? g_t : g_h1;
    float* __restrict__ acc      = pass ? g_a2 : g_a1;

    unsigned n = blockIdx.x * 8 + (threadIdx.x >> 5);   // 12500 * 8 = 100000 exactly
    unsigned l = threadIdx.x & 31;
    unsigned g = l >> 2, c = l & 3;
    int end = __ldg(&g_end[n]);
    int e = (int)(n * ROW) + (int)g;

    float4 a0 = make_float4(0.f, 0.f, 0.f, 0.f);
    float4 a1 = make_float4(0.f, 0.f, 0.f, 0.f);
    float4 a2 = make_float4(0.f, 0.f, 0.f, 0.f);
    float4 a3 = make_float4(0.f, 0.f, 0.f, 0.f);
    for (; e + 24 < end; e += 32) {                // four edges in flight per group
        int s0 = __ldg(&g_csrc[e]);
        int s1 = __ldg(&g_csrc[e + 8]);
        int s2 = __ldg(&g_csrc[e + 16]);
        int s3 = __ldg(&g_csrc[e + 24]);
        float4 h0 = ld_h4(h + (size_t)s0 * 16 + c * 4);
        float4 h1 = ld_h4(h + (size_t)s1 * 16 + c * 4);
        float4 h2 = ld_h4(h + (size_t)s2 * 16 + c * 4);
        float4 h3 = ld_h4(h + (size_t)s3 * 16 + c * 4);
        a0.x += h0.x; a0.y += h0.y; a0.z += h0.z; a0.w += h0.w;
        a1.x += h1.x; a1.y += h1.y; a1.z += h1.z; a1.w += h1.w;
        a2.x += h2.x; a2.y += h2.y; a2.z += h2.z; a2.w += h2.w;
        a3.x += h3.x; a3.y += h3.y; a3.z += h3.z; a3.w += h3.w;
    }
    for (; e < end; e += 8) {
        int s = __ldg(&g_csrc[e]);
        float4 hv = ld_h4(h + (size_t)s * 16 + c * 4);
        a0.x += hv.x; a0.y += hv.y; a0.z += hv.z; a0.w += hv.w;
    }
    a0.x += a1.x + a2.x + a3.x;
    a0.y += a1.y + a2.y + a3.y;
    a0.z += a1.z + a2.z + a3.z;
    a0.w += a1.w + a2.w + a3.w;

#pragma unroll
    for (int d = 4; d < 32; d <<= 1) {
        a0.x += __shfl_xor_sync(0xffffffffu, a0.x, d);
        a0.y += __shfl_xor_sync(0xffffffffu, a0.y, d);
        a0.z += __shfl_xor_sync(0xffffffffu, a0.z, d);
        a0.w += __shfl_xor_sync(0xffffffffu, a0.w, d);
    }
    if (l < 4) {
        float4 hv = ld_h4(h + (size_t)n * 16 + c * 4);   // self-loop
        a0.x += hv.x; a0.y += hv.y; a0.z += hv.z; a0.w += hv.w;
        *(float4*)(acc + (size_t)n * 16 + c * 4) = a0;
    }
}

// ---------------- post conv1: dinv*sum + b1, relu, dropout(dk1), @W2, prescale, fp16 out ----------------
__global__ void k_post1(const float* __restrict__ b1, const float* __restrict__ W2,
                        uint32_t k0, uint32_t k1)
{
    __shared__ float w2s[256];
    unsigned tid = threadIdx.x;
    w2s[tid] = W2[tid];
    __syncthreads();

    unsigned idx = blockIdx.x * blockDim.x + tid;   // grid covers TOT exactly
    unsigned n = idx >> 4, j = idx & 15;
    float di = g_dinv[n];
    float v = fmaxf(fmaf(di, g_a1[idx], b1[j]), 0.0f);
    v = dropout_elem(v, k0, k1, idx);

    float acc = 0.0f;
#pragma unroll
    for (int jj = 0; jj < 16; ++jj) {
        float hv = __shfl_sync(0xffffffffu, v, jj, 16);
        acc = fmaf(hv, w2s[jj * 16 + j], acc);
    }
    acc *= di;
    float acc2 = __shfl_down_sync(0xffffffffu, acc, 1);
    if (!(j & 1))
        *(__half2*)(g_t + (size_t)n * 16 + j) = __floats2half2_rn(acc, acc2);
}

// ---------------- final: dinv*sum + b2, relu, dropout(dk2) -> out ----------------
__global__ void k_final(float* __restrict__ out, const float* __restrict__ b2,
                        uint32_t k0, uint32_t k1)
{
    unsigned idx = blockIdx.x * blockDim.x + threadIdx.x;   // covers TOT exactly
    unsigned n = idx >> 4, j = idx & 15;
    float v = fmaxf(fmaf(g_dinv[n], g_a2[idx], b2[j]), 0.0f);
    out[idx] = dropout_elem(v, k0, k1, idx);
}

// ---------------- launch ----------------
extern "C" void kernel_launch(void* const* d_in, const int* in_sizes, int n_in,
                              void* d_out, int out_size)
{
    const float* x     = (const float*)d_in[0];
    const int*   ei    = (const int*)d_in[1];
    const float* gamma = (const float*)d_in[2];
    const float* beta  = (const float*)d_in[3];
    const float* W1    = (const float*)d_in[4];
    const float* b1    = (const float*)d_in[5];
    const float* W2    = (const float*)d_in[6];
    const float* b2    = (const float*)d_in[7];
    float* out = (float*)d_out;

    const int4* src4 = (const int4*)ei;            // edge_index[0]
    const int4* dst4 = (const int4*)(ei + NE);     // edge_index[1]

    // JAX partitionable split: dk1 = threefry(key,(0,0)), dk2 = threefry(key,(0,1))
    uint32_t A0, A1, B0, B1;
    threefry2x32(0u, 42u, 0u, 0u, A0, A1);
    threefry2x32(0u, 42u, 0u, 1u, B0, B1);

    k_fill<<<NE / 8 / 256, 256>>>(src4, dst4);
    k_dinv<<<NB1, 256>>>();
    k_ln_gemm<<<444, 256>>>(x, gamma, beta, W1);
    k_gather<<<12500, 256>>>(0);
    k_post1<<<TOT / 256, 256>>>(b1, W2, A0, A1);
    k_gather<<<12500, 256>>>(1);
    k_final<<<TOT / 256, 256>>>(out, b2, B0, B1);
}

// round 17
// speedup vs baseline: 1.0229x; 1.0042x over previous
#include <cuda_runtime.h>
#include <cuda_fp16.h>
#include <cstdint>

#define NN 100000
#define NE 6400000
#define DIN 128
#define HID 16
#define TOT (NN * HID)
#define ROW 128            // padded CSR row capacity (deg ~ Poisson(64); P(>128) ~ 1e-15)
#define NB1 391            // ceil(NN/256)

// ---------------- scratch (static device globals; no allocation) ----------------
__device__ __align__(16) __half g_h1[TOT];   // fp16: dinv[n] * (xn @ W1)
__device__ __align__(16) __half g_t[TOT];    // fp16: dinv[n] * (dropout(relu(conv1)) @ W2)
__device__ __align__(16) float  g_a1[TOT];   // conv1 gather sums (fp32)
__device__ __align__(16) float  g_a2[TOT];   // conv2 gather sums (fp32)
__device__ float g_dinv[NN];
__device__ int   g_cnt[NN];                  // fill cursor / degree; re-zeroed each replay
__device__ int   g_end[NN];                  // absolute row end = n*ROW + deg
__device__ int   g_csrc[NN * ROW];           // padded CSR: src per slot (51.2 MB)

// ---------------- JAX Threefry-2x32 (20 rounds), bit-exact ----------------
__host__ __device__ __forceinline__ void threefry2x32(
    uint32_t k0, uint32_t k1, uint32_t x0, uint32_t x1,
    uint32_t& o0, uint32_t& o1)
{
    uint32_t ks2 = k0 ^ k1 ^ 0x1BD11BDAu;
    x0 += k0; x1 += k1;
#define TF_R(r) { x0 += x1; x1 = (x1 << r) | (x1 >> (32 - r)); x1 ^= x0; }
    TF_R(13) TF_R(15) TF_R(26) TF_R(6)
    x0 += k1;  x1 += ks2 + 1u;
    TF_R(17) TF_R(29) TF_R(16) TF_R(24)
    x0 += ks2; x1 += k0 + 2u;
    TF_R(13) TF_R(15) TF_R(26) TF_R(6)
    x0 += k0;  x1 += k1 + 3u;
    TF_R(17) TF_R(29) TF_R(16) TF_R(24)
    x0 += k1;  x1 += ks2 + 4u;
    TF_R(13) TF_R(15) TF_R(26) TF_R(6)
    x0 += ks2; x1 += k0 + 5u;
#undef TF_R
    o0 = x0; o1 = x1;
}

// Partitionable-mode random_bits: counter (0, i); output = o0 ^ o1.
__device__ __forceinline__ float dropout_elem(float h, uint32_t k0, uint32_t k1, uint32_t i)
{
    uint32_t o0, o1;
    threefry2x32(k0, k1, 0u, i, o0, o1);
    uint32_t bits = o0 ^ o1;
    float u = __uint_as_float((bits >> 9) | 0x3F800000u) - 1.0f;
    return (u >= 0.3f) ? (h / 0.7f) : 0.0f;
}

// load 4 consecutive halfs (8B) -> float4
__device__ __forceinline__ float4 ld_h4(const __half* p)
{
    uint2 r = *(const uint2*)p;
    __half2 h0 = *(__half2*)&r.x, h1 = *(__half2*)&r.y;
    float2 f0 = __half22float2(h0), f1 = __half22float2(h1);
    return make_float4(f0.x, f0.y, f1.x, f1.y);
}

// ---------------- padded CSR fill: 2x int4 per thread = 8 atomic chains in flight ----------------
__global__ void k_fill(const int4* __restrict__ src4, const int4* __restrict__ dst4)
{
    unsigned i = blockIdx.x * blockDim.x + threadIdx.x;   // grid covers NE/8 exactly
    const unsigned OFS = NE / 8;                          // 800000 int4 elements
    int4 s0 = src4[i],       d0 = dst4[i];
    int4 s1 = src4[i + OFS], d1 = dst4[i + OFS];

    int p0 = atomicAdd(&g_cnt[d0.x], 1);
    int p1 = atomicAdd(&g_cnt[d0.y], 1);
    int p2 = atomicAdd(&g_cnt[d0.z], 1);
    int p3 = atomicAdd(&g_cnt[d0.w], 1);
    int p4 = atomicAdd(&g_cnt[d1.x], 1);
    int p5 = atomicAdd(&g_cnt[d1.y], 1);
    int p6 = atomicAdd(&g_cnt[d1.z], 1);
    int p7 = atomicAdd(&g_cnt[d1.w], 1);

    if (p0 < ROW) g_csrc[(size_t)d0.x * ROW + p0] = s0.x;
    if (p1 < ROW) g_csrc[(size_t)d0.y * ROW + p1] = s0.y;
    if (p2 < ROW) g_csrc[(size_t)d0.z * ROW + p2] = s0.z;
    if (p3 < ROW) g_csrc[(size_t)d0.w * ROW + p3] = s0.w;
    if (p4 < ROW) g_csrc[(size_t)d1.x * ROW + p4] = s1.x;
    if (p5 < ROW) g_csrc[(size_t)d1.y * ROW + p5] = s1.y;
    if (p6 < ROW) g_csrc[(size_t)d1.z * ROW + p6] = s1.z;
    if (p7 < ROW) g_csrc[(size_t)d1.w * ROW + p7] = s1.w;
}

// degree -> dinv + row end; re-zero cnt (replay invariant)
__global__ void k_dinv()
{
    unsigned i = blockIdx.x * blockDim.x + threadIdx.x;
    if (i < NN) {
        int c = g_cnt[i];
        g_end[i] = (int)(i * ROW) + c;
        g_dinv[i] = rsqrtf((float)(c + 1));   // +1 self-loop
        g_cnt[i] = 0;
    }
}

// ---------------- LayerNorm + GEMM1 (warp per node), 4-stage pipeline, fp16 W cache --------------
// 3 x-rows outstanding per warp during compute -> ~24KB/SM in flight at 2 CTAs/SM.
__global__ __launch_bounds__(256, 2) void k_ln_gemm(
    const float* __restrict__ x,
    const float* __restrict__ gamma, const float* __restrict__ beta,
    const float* __restrict__ W1)
{
    unsigned l = threadIdx.x & 31;
    unsigned warp = blockIdx.x * (blockDim.x >> 5) + (threadIdx.x >> 5);
    unsigned nwarps = gridDim.x * (blockDim.x >> 5);

    float4 g4 = *(const float4*)(gamma + l * 4);
    float4 b4 = *(const float4*)(beta + l * 4);
    // W1 rows 4l..4l+3 cached as fp16 (32 regs instead of 64)
    __half2 w[32];
#pragma unroll
    for (int c = 0; c < 4; ++c)
#pragma unroll
        for (int q = 0; q < 4; ++q) {
            float4 wv = *(const float4*)(W1 + (size_t)(l * 4 + c) * 16 + q * 4);
            w[(c * 4 + q) * 2 + 0] = __floats2half2_rn(wv.x, wv.y);
            w[(c * 4 + q) * 2 + 1] = __floats2half2_rn(wv.z, wv.w);
        }

    const float4 Z4 = make_float4(0.f, 0.f, 0.f, 0.f);
    float4 x0 = Z4, x1 = Z4, x2 = Z4;
    float d0 = 0.f, d1 = 0.f, d2 = 0.f;

    unsigned n = warp;
    if (n < NN) {
        x0 = *(const float4*)(x + (size_t)n * DIN + l * 4);
        d0 = g_dinv[n];
    }
    unsigned nb = n + nwarps;
    if (nb < NN) {
        x1 = *(const float4*)(x + (size_t)nb * DIN + l * 4);
        d1 = g_dinv[nb];
    }
    unsigned nc = nb + nwarps;
    if (nc < NN) {
        x2 = *(const float4*)(x + (size_t)nc * DIN + l * 4);
        d2 = g_dinv[nc];
    }

    while (n < NN) {
        // prefetch node n + 3*step while computing node n
        unsigned nd = n + 3 * nwarps;
        float4 x3 = Z4;
        float d3 = 0.f;
        if (nd < NN) {
            x3 = *(const float4*)(x + (size_t)nd * DIN + l * 4);
            d3 = g_dinv[nd];
        }

        float4 xv = x0;
        float di = d0;

        float s  = xv.x + xv.y + xv.z + xv.w;
        float ss = xv.x * xv.x + xv.y * xv.y + xv.z * xv.z + xv.w * xv.w;
#pragma unroll
        for (int d = 16; d >= 1; d >>= 1) {
            s  += __shfl_xor_sync(0xffffffffu, s,  d);
            ss += __shfl_xor_sync(0xffffffffu, ss, d);
        }
        float mu  = s * (1.0f / 128.0f);
        float var = ss * (1.0f / 128.0f) - mu * mu;
        float rs  = rsqrtf(var + 1e-5f);

        float xn[4];
        xn[0] = (xv.x - mu) * rs * g4.x + b4.x;
        xn[1] = (xv.y - mu) * rs * g4.y + b4.y;
        xn[2] = (xv.z - mu) * rs * g4.z + b4.z;
        xn[3] = (xv.w - mu) * rs * g4.w + b4.w;

        float p[16];
#pragma unroll
        for (int j = 0; j < 16; ++j) p[j] = 0.0f;
#pragma unroll
        for (int c = 0; c < 4; ++c) {
#pragma unroll
            for (int q = 0; q < 4; ++q) {
                float2 wa = __half22float2(w[(c * 4 + q) * 2 + 0]);
                float2 wb = __half22float2(w[(c * 4 + q) * 2 + 1]);
                p[q * 4 + 0] = fmaf(xn[c], wa.x, p[q * 4 + 0]);
                p[q * 4 + 1] = fmaf(xn[c], wa.y, p[q * 4 + 1]);
                p[q * 4 + 2] = fmaf(xn[c], wb.x, p[q * 4 + 2]);
                p[q * 4 + 3] = fmaf(xn[c], wb.y, p[q * 4 + 3]);
            }
        }
        {
            bool hi;
#define RED_STEP(D, M)                                                        \
            hi = (l & D) != 0;                                                \
            _Pragma("unroll")                                                 \
            for (int i = 0; i < M; ++i) {                                     \
                float send  = hi ? p[i] : p[i + M];                           \
                float other = __shfl_xor_sync(0xffffffffu, send, D);          \
                float keep  = hi ? p[i + M] : p[i];                           \
                p[i] = keep + other;                                          \
            }
            RED_STEP(16, 8) RED_STEP(8, 4) RED_STEP(4, 2) RED_STEP(2, 1)
#undef RED_STEP
            p[0] += __shfl_xor_sync(0xffffffffu, p[0], 1);
        }
        // all lanes hold feature (l>>1); pack fp16 pairs on lanes with l%4==0
        {
            float val = p[0] * di;
            float vnx = __shfl_down_sync(0xffffffffu, val, 2);
            if ((l & 3) == 0)
                *(__half2*)(g_h1 + (size_t)n * 16 + (l >> 1)) = __floats2half2_rn(val, vnx);
        }

        n += nwarps;
        x0 = x1; d0 = d1;
        x1 = x2; d1 = d2;
        x2 = x3; d2 = d3;
    }
}

// ---------------- CSR gather (fp16 h): warp per dst node, 4 lanes/edge, 4x unroll ----------------
// pass=0: h=g_h1 acc=g_a1 ; pass=1: h=g_t acc=g_a2 (selected DEVICE-side)
__global__ __launch_bounds__(256) void k_gather(int pass)
{
    const __half* __restrict__ h = pass ? g_t : g_h1;
    float* __restrict__ acc      = pass ? g_a2 : g_a1;

    unsigned n = blockIdx.x * 8 + (threadIdx.x >> 5);   // 12500 * 8 = 100000 exactly
    unsigned l = threadIdx.x & 31;
    unsigned g = l >> 2, c = l & 3;
    int end = __ldg(&g_end[n]);
    int e = (int)(n * ROW) + (int)g;

    float4 a0 = make_float4(0.f, 0.f, 0.f, 0.f);
    float4 a1 = make_float4(0.f, 0.f, 0.f, 0.f);
    float4 a2 = make_float4(0.f, 0.f, 0.f, 0.f);
    float4 a3 = make_float4(0.f, 0.f, 0.f, 0.f);
    for (; e + 24 < end; e += 32) {                // four edges in flight per group
        int s0 = __ldg(&g_csrc[e]);
        int s1 = __ldg(&g_csrc[e + 8]);
        int s2 = __ldg(&g_csrc[e + 16]);
        int s3 = __ldg(&g_csrc[e + 24]);
        float4 h0 = ld_h4(h + (size_t)s0 * 16 + c * 4);
        float4 h1 = ld_h4(h + (size_t)s1 * 16 + c * 4);
        float4 h2 = ld_h4(h + (size_t)s2 * 16 + c * 4);
        float4 h3 = ld_h4(h + (size_t)s3 * 16 + c * 4);
        a0.x += h0.x; a0.y += h0.y; a0.z += h0.z; a0.w += h0.w;
        a1.x += h1.x; a1.y += h1.y; a1.z += h1.z; a1.w += h1.w;
        a2.x += h2.x; a2.y += h2.y; a2.z += h2.z; a2.w += h2.w;
        a3.x += h3.x; a3.y += h3.y; a3.z += h3.z; a3.w += h3.w;
    }
    for (; e < end; e += 8) {
        int s = __ldg(&g_csrc[e]);
        float4 hv = ld_h4(h + (size_t)s * 16 + c * 4);
        a0.x += hv.x; a0.y += hv.y; a0.z += hv.z; a0.w += hv.w;
    }
    a0.x += a1.x + a2.x + a3.x;
    a0.y += a1.y + a2.y + a3.y;
    a0.z += a1.z + a2.z + a3.z;
    a0.w += a1.w + a2.w + a3.w;

#pragma unroll
    for (int d = 4; d < 32; d <<= 1) {
        a0.x += __shfl_xor_sync(0xffffffffu, a0.x, d);
        a0.y += __shfl_xor_sync(0xffffffffu, a0.y, d);
        a0.z += __shfl_xor_sync(0xffffffffu, a0.z, d);
        a0.w += __shfl_xor_sync(0xffffffffu, a0.w, d);
    }
    if (l < 4) {
        float4 hv = ld_h4(h + (size_t)n * 16 + c * 4);   // self-loop
        a0.x += hv.x; a0.y += hv.y; a0.z += hv.z; a0.w += hv.w;
        *(float4*)(acc + (size_t)n * 16 + c * 4) = a0;
    }
}

// ---------------- post conv1: dinv*sum + b1, relu, dropout(dk1), @W2, prescale, fp16 out ----------------
__global__ void k_post1(const float* __restrict__ b1, const float* __restrict__ W2,
                        uint32_t k0, uint32_t k1)
{
    __shared__ float w2s[256];
    unsigned tid = threadIdx.x;
    w2s[tid] = W2[tid];
    __syncthreads();

    unsigned idx = blockIdx.x * blockDim.x + tid;   // grid covers TOT exactly
    unsigned n = idx >> 4, j = idx & 15;
    float di = g_dinv[n];
    float v = fmaxf(fmaf(di, g_a1[idx], b1[j]), 0.0f);
    v = dropout_elem(v, k0, k1, idx);

    float acc = 0.0f;
#pragma unroll
    for (int jj = 0; jj < 16; ++jj) {
        float hv = __shfl_sync(0xffffffffu, v, jj, 16);
        acc = fmaf(hv, w2s[jj * 16 + j], acc);
    }
    acc *= di;
    float acc2 = __shfl_down_sync(0xffffffffu, acc, 1);
    if (!(j & 1))
        *(__half2*)(g_t + (size_t)n * 16 + j) = __floats2half2_rn(acc, acc2);
}

// ---------------- final: dinv*sum + b2, relu, dropout(dk2) -> out ----------------
__global__ void k_final(float* __restrict__ out, const float* __restrict__ b2,
                        uint32_t k0, uint32_t k1)
{
    unsigned idx = blockIdx.x * blockDim.x + threadIdx.x;   // covers TOT exactly
    unsigned n = idx >> 4, j = idx & 15;
    float v = fmaxf(fmaf(g_dinv[n], g_a2[idx], b2[j]), 0.0f);
    out[idx] = dropout_elem(v, k0, k1, idx);
}

// ---------------- launch ----------------
extern "C" void kernel_launch(void* const* d_in, const int* in_sizes, int n_in,
                              void* d_out, int out_size)
{
    const float* x     = (const float*)d_in[0];
    const int*   ei    = (const int*)d_in[1];
    const float* gamma = (const float*)d_in[2];
    const float* beta  = (const float*)d_in[3];
    const float* W1    = (const float*)d_in[4];
    const float* b1    = (const float*)d_in[5];
    const float* W2    = (const float*)d_in[6];
    const float* b2    = (const float*)d_in[7];
    float* out = (float*)d_out;

    const int4* src4 = (const int4*)ei;            // edge_index[0]
    const int4* dst4 = (const int4*)(ei + NE);     // edge_index[1]

    // JAX partitionable split: dk1 = threefry(key,(0,0)), dk2 = threefry(key,(0,1))
    uint32_t A0, A1, B0, B1;
    threefry2x32(0u, 42u, 0u, 0u, A0, A1);
    threefry2x32(0u, 42u, 0u, 1u, B0, B1);

    k_fill<<<NE / 8 / 256, 256>>>(src4, dst4);
    k_dinv<<<NB1, 256>>>();
    k_ln_gemm<<<296, 256>>>(x, gamma, beta, W1);
    k_gather<<<12500, 256>>>(0);
    k_post1<<<TOT / 256, 256>>>(b1, W2, A0, A1);
    k_gather<<<12500, 256>>>(1);
    k_final<<<TOT / 256, 256>>>(out, b2, B0, B1);
}